// round 1
// baseline (speedup 1.0000x reference)
#include <cuda_runtime.h>
#include <cstdint>

#define AN 13824          // 24*24*24 anchors
#define NT 512            // threads per block
#define PER 27            // AN / NT
#define TK 60             // TOPK
#define NMSK 20           // NMS_TOPK

__device__ __forceinline__ unsigned int fkey(float x) {
    unsigned int b = __float_as_uint(x);
    return (b & 0x80000000u) ? ~b : (b | 0x80000000u);
}
__device__ __forceinline__ float fkey_inv(unsigned int u) {
    unsigned int b = (u & 0x80000000u) ? (u & 0x7fffffffu) : ~u;
    return __uint_as_float(b);
}
__device__ __forceinline__ unsigned long long umax64(unsigned long long a, unsigned long long b) {
    return a > b ? a : b;
}

__global__ __launch_bounds__(NT, 2)
void detect_postproc_kernel(const float* __restrict__ cls,
                            const float* __restrict__ shp,
                            const float* __restrict__ off,
                            float* __restrict__ out)
{
    const int b    = blockIdx.x;
    const int t    = threadIdx.x;
    const int lane = t & 31;
    const int wid  = t >> 5;

    __shared__ unsigned long long s_wmax[16];
    __shared__ unsigned long long s_win;
    __shared__ int   s_idx[TK];
    __shared__ float s_sc[TK];
    __shared__ float s_ctr[TK][3];
    __shared__ float s_sz[TK][3];
    __shared__ float s_lo[TK][3];
    __shared__ float s_hi[TK][3];
    __shared__ float s_vol[TK];
    __shared__ float s_iou[TK * TK];
    __shared__ int   s_cand[TK], s_kept[TK], s_supp[TK];
    __shared__ int   s_src[TK];
    __shared__ int   s_nk;

    // ---------------- Phase 1: load logits as sortable keys ----------------
    unsigned int keys[PER];
    const float* cb = cls + (size_t)b * AN;
#pragma unroll
    for (int j = 0; j < PER; j++)
        keys[j] = fkey(cb[t + NT * j]);

    unsigned long long best = 0ull;
#pragma unroll
    for (int j = 0; j < PER; j++) {
        unsigned long long k =
            ((unsigned long long)keys[j] << 14) |
            (unsigned long long)(16383 - (t + NT * j));
        best = umax64(best, k);
    }

    // ---------------- Phase 2: extract top-60 via block argmax ----------------
    for (int i = 0; i < TK; i++) {
        unsigned long long v = best;
#pragma unroll
        for (int o = 16; o; o >>= 1)
            v = umax64(v, __shfl_xor_sync(0xffffffffu, v, o));
        if (lane == 0) s_wmax[wid] = v;
        __syncthreads();
        if (wid == 0) {
            unsigned long long v2 = (lane < 16) ? s_wmax[lane] : 0ull;
#pragma unroll
            for (int o = 8; o; o >>= 1)
                v2 = umax64(v2, __shfl_xor_sync(0xffffffffu, v2, o));
            if (lane == 0) {
                s_win = v2;
                int idx = 16383 - (int)(v2 & 16383ull);
                s_idx[i] = idx;
                float logit = fkey_inv((unsigned int)(v2 >> 14));
                s_sc[i] = 1.0f / (1.0f + expf(-logit));
            }
        }
        __syncthreads();
        unsigned long long w = s_win;
        int idx = 16383 - (int)(w & 16383ull);
        if ((idx & (NT - 1)) == t) {
            keys[(idx - t) >> 9] = 0u;  // invalidate (valid keys are never 0 for finite inputs)
            best = 0ull;
#pragma unroll
            for (int j = 0; j < PER; j++) {
                if (keys[j]) {
                    unsigned long long k =
                        ((unsigned long long)keys[j] << 14) |
                        (unsigned long long)(16383 - (t + NT * j));
                    best = umax64(best, k);
                }
            }
        }
    }

    // ---------------- Phase 3: gather boxes for top-60 ----------------
    if (t < TK) {
        int idx = s_idx[t];
        int z   = idx / 576;
        int rem = idx - z * 576;
        int y   = rem / 24;
        int x   = rem - y * 24;
        size_t base = (size_t)b * 3 * AN;
        float oz = off[base + 0 * AN + idx];
        float oy = off[base + 1 * AN + idx];
        float ox = off[base + 2 * AN + idx];
        float s0 = shp[base + 0 * AN + idx];
        float s1 = shp[base + 1 * AN + idx];
        float s2 = shp[base + 2 * AN + idx];
        // strides = 96/24 = 4 exactly
        float cz = ((float)z + oz) * 4.0f;
        float cy = ((float)y + oy) * 4.0f;
        float cx = ((float)x + ox) * 4.0f;
        float dz = 2.0f * s0, dy = 2.0f * s1, dx = 2.0f * s2;
        s_ctr[t][0] = cz; s_ctr[t][1] = cy; s_ctr[t][2] = cx;
        s_sz[t][0]  = dz; s_sz[t][1]  = dy; s_sz[t][2]  = dx;
        s_lo[t][0] = cz - dz * 0.5f; s_lo[t][1] = cy - dy * 0.5f; s_lo[t][2] = cx - dx * 0.5f;
        s_hi[t][0] = cz + dz * 0.5f; s_hi[t][1] = cy + dy * 0.5f; s_hi[t][2] = cx + dx * 0.5f;
        s_vol[t] = dz * dy * dx;
        s_supp[t] = 0;
        s_kept[t] = 0;
    }
    __syncthreads();

    // ---------------- Phase 4: IoU matrix ----------------
    if (t < TK) {
        float l0 = s_lo[t][0], l1 = s_lo[t][1], l2 = s_lo[t][2];
        float h0 = s_hi[t][0], h1 = s_hi[t][1], h2 = s_hi[t][2];
        float vi = s_vol[t];
        for (int j = 0; j < TK; j++) {
            float iz = fminf(h0, s_hi[j][0]) - fmaxf(l0, s_lo[j][0]);
            float iy = fminf(h1, s_hi[j][1]) - fmaxf(l1, s_lo[j][1]);
            float ix = fminf(h2, s_hi[j][2]) - fmaxf(l2, s_lo[j][2]);
            float inter = fmaxf(iz, 0.0f) * fmaxf(iy, 0.0f) * fmaxf(ix, 0.0f);
            float uni = vi + s_vol[j] - inter;
            s_iou[t * TK + j] = inter / fmaxf(uni, 1e-8f);
        }
    }
    __syncthreads();

    // ---------------- Phase 5: sequential NMS on warp 0 ----------------
    if (wid == 0) {
        if (lane == 0) {
            int r = 0;
            for (int i = 0; i < TK; i++) {
                int v = s_sc[i] > 0.15f;
                s_cand[i] = v && (r < NMSK);
                r += v;
            }
        }
        __syncwarp();
        for (int i = 0; i < TK; i++) {
            int keep = s_cand[i] && !s_supp[i];
            if (lane == 0) s_kept[i] = keep;
            if (keep) {
                for (int m = lane; m < TK; m += 32)
                    if (m != i && s_iou[i * TK + m] > 0.05f) s_supp[m] = 1;
            }
            __syncwarp();
        }
        if (lane == 0) {
            int nk = 0;
            for (int i = 0; i < TK; i++)
                if (s_kept[i]) s_src[nk++] = i;
            s_nk = nk;
        }
    }
    __syncthreads();

    // ---------------- Phase 6: write output (kept-first, -1 padding) ----------------
    float* ob = out + (size_t)b * TK * 8;
    if (t < TK) {
        if (t < s_nk) {
            int i = s_src[t];
            ob[t * 8 + 0] = 1.0f;
            ob[t * 8 + 1] = s_sc[i];
            ob[t * 8 + 2] = s_ctr[i][0];
            ob[t * 8 + 3] = s_ctr[i][1];
            ob[t * 8 + 4] = s_ctr[i][2];
            ob[t * 8 + 5] = s_sz[i][0];
            ob[t * 8 + 6] = s_sz[i][1];
            ob[t * 8 + 7] = s_sz[i][2];
        } else {
#pragma unroll
            for (int c = 0; c < 8; c++)
                ob[t * 8 + c] = -1.0f;
        }
    }
}

extern "C" void kernel_launch(void* const* d_in, const int* in_sizes, int n_in,
                              void* d_out, int out_size)
{
    const float* cls = (const float*)d_in[0];
    const float* shp = (const float*)d_in[1];
    const float* off = (const float*)d_in[2];
    float* out = (float*)d_out;
    detect_postproc_kernel<<<256, NT>>>(cls, shp, off, out);
}

// round 2
// speedup vs baseline: 2.4480x; 2.4480x over previous
#include <cuda_runtime.h>
#include <cstdint>

#define AN 13824          // 24*24*24 anchors
#define NT 512            // threads per block
#define PER 27            // AN / NT
#define TK 60             // TOPK
#define NMSK 20           // NMS_TOPK
#define NBIN 2048         // histogram bins (top 11 bits of fkey)
#define CAP 1024          // candidate capacity

__device__ __forceinline__ unsigned int fkey(float x) {
    unsigned int b = __float_as_uint(x);
    return (b & 0x80000000u) ? ~b : (b | 0x80000000u);
}
__device__ __forceinline__ float fkey_inv(unsigned int u) {
    unsigned int b = (u & 0x80000000u) ? (u & 0x7fffffffu) : ~u;
    return __uint_as_float(b);
}

__global__ __launch_bounds__(NT, 2)
void detect_postproc_kernel(const float* __restrict__ cls,
                            const float* __restrict__ shp,
                            const float* __restrict__ off,
                            float* __restrict__ out)
{
    const int b    = blockIdx.x;
    const int t    = threadIdx.x;
    const int lane = t & 31;
    const int wid  = t >> 5;

    __shared__ int   s_hist[NBIN];
    __shared__ int   s_part[NT];
    __shared__ unsigned long long s_cand[CAP];
    __shared__ int   s_ncand;
    __shared__ int   s_cutbin;
    __shared__ int   s_idx[TK];
    __shared__ float s_sc[TK];
    __shared__ float s_ctr[TK][3];
    __shared__ float s_sz[TK][3];
    __shared__ float s_lo[TK][3];
    __shared__ float s_hi[TK][3];
    __shared__ float s_vol[TK];
    __shared__ float s_iou[TK * TK];
    __shared__ int   s_candf[TK], s_kept[TK], s_supp[TK];
    __shared__ int   s_src[TK];
    __shared__ int   s_nk;

    // ---------------- Phase 1: load logits as sortable keys, histogram ----------------
    unsigned int keys[PER];
    const float* cb = cls + (size_t)b * AN;
#pragma unroll
    for (int j = 0; j < PER; j++)
        keys[j] = fkey(cb[t + NT * j]);

#pragma unroll
    for (int j = 0; j < 4; j++)
        s_hist[t + NT * j] = 0;
    if (t == 0) s_ncand = 0;
    __syncthreads();

#pragma unroll
    for (int j = 0; j < PER; j++)
        atomicAdd(&s_hist[keys[j] >> 21], 1);
    __syncthreads();

    // per-thread partial: bins [t*4, t*4+4)
    {
        int p = s_hist[t * 4 + 0] + s_hist[t * 4 + 1] + s_hist[t * 4 + 2] + s_hist[t * 4 + 3];
        s_part[t] = p;
    }
    __syncthreads();

    // ---------------- Phase 2: warp 0 finds cutoff bin (top-down) ----------------
    if (wid == 0) {
        int g = 0;
#pragma unroll
        for (int j = 0; j < 16; j++)
            g += s_part[lane * 16 + j];
        // inclusive suffix sum from top lane down
        int incl = g;
#pragma unroll
        for (int o = 1; o < 32; o <<= 1) {
            int v = __shfl_down_sync(0xffffffffu, incl, o);
            if (lane + o < 32) incl += v;
        }
        int excl = incl - g;   // count in groups above this lane's group
        bool cross = (excl < TK) && (incl >= TK);
        if (cross) {
            int cum = excl;
            int bfound = 0;
            for (int p = 15; p >= 0; p--) {
                int part = s_part[lane * 16 + p];
                if (cum + part >= TK) {
                    int base = (lane * 16 + p) * 4;
                    for (int q = 3; q >= 0; q--) {
                        int h = s_hist[base + q];
                        if (cum + h >= TK) { bfound = base + q; break; }
                        cum += h;
                    }
                    break;
                }
                cum += part;
            }
            s_cutbin = bfound;
        }
    }
    __syncthreads();

    // ---------------- Phase 3: collect candidates (bin >= cutoff) ----------------
    {
        const unsigned int cut = (unsigned int)s_cutbin;
#pragma unroll
        for (int j = 0; j < PER; j++) {
            if ((keys[j] >> 21) >= cut) {
                int pos = atomicAdd(&s_ncand, 1);
                if (pos < CAP) {
                    int idx = t + NT * j;
                    s_cand[pos] = ((unsigned long long)keys[j] << 14) |
                                  (unsigned long long)(16383 - idx);
                }
            }
        }
    }
    __syncthreads();

    // ---------------- Phase 4: exact ranking of candidates ----------------
    {
        int C = s_ncand;
        if (C > CAP) C = CAP;
        for (int c = t; c < C; c += NT) {
            unsigned long long k = s_cand[c];
            int r = 0;
            for (int m = 0; m < C; m++)
                r += (s_cand[m] > k);
            if (r < TK) {
                int idx = 16383 - (int)(k & 16383ull);
                float logit = fkey_inv((unsigned int)(k >> 14));
                s_idx[r] = idx;
                s_sc[r] = 1.0f / (1.0f + expf(-logit));
            }
        }
    }
    __syncthreads();

    // ---------------- Phase 5: gather boxes for top-60 ----------------
    if (t < TK) {
        int idx = s_idx[t];
        int z   = idx / 576;
        int rem = idx - z * 576;
        int y   = rem / 24;
        int x   = rem - y * 24;
        size_t base = (size_t)b * 3 * AN;
        float oz = off[base + 0 * AN + idx];
        float oy = off[base + 1 * AN + idx];
        float ox = off[base + 2 * AN + idx];
        float s0 = shp[base + 0 * AN + idx];
        float s1 = shp[base + 1 * AN + idx];
        float s2 = shp[base + 2 * AN + idx];
        // strides = 96/24 = 4 exactly
        float cz = ((float)z + oz) * 4.0f;
        float cy = ((float)y + oy) * 4.0f;
        float cx = ((float)x + ox) * 4.0f;
        float dz = 2.0f * s0, dy = 2.0f * s1, dx = 2.0f * s2;
        s_ctr[t][0] = cz; s_ctr[t][1] = cy; s_ctr[t][2] = cx;
        s_sz[t][0]  = dz; s_sz[t][1]  = dy; s_sz[t][2]  = dx;
        s_lo[t][0] = cz - dz * 0.5f; s_lo[t][1] = cy - dy * 0.5f; s_lo[t][2] = cx - dx * 0.5f;
        s_hi[t][0] = cz + dz * 0.5f; s_hi[t][1] = cy + dy * 0.5f; s_hi[t][2] = cx + dx * 0.5f;
        s_vol[t] = dz * dy * dx;
        s_supp[t] = 0;
        s_kept[t] = 0;
    }
    __syncthreads();

    // ---------------- Phase 6: IoU matrix ----------------
    if (t < TK) {
        float l0 = s_lo[t][0], l1 = s_lo[t][1], l2 = s_lo[t][2];
        float h0 = s_hi[t][0], h1 = s_hi[t][1], h2 = s_hi[t][2];
        float vi = s_vol[t];
        for (int j = 0; j < TK; j++) {
            float iz = fminf(h0, s_hi[j][0]) - fmaxf(l0, s_lo[j][0]);
            float iy = fminf(h1, s_hi[j][1]) - fmaxf(l1, s_lo[j][1]);
            float ix = fminf(h2, s_hi[j][2]) - fmaxf(l2, s_lo[j][2]);
            float inter = fmaxf(iz, 0.0f) * fmaxf(iy, 0.0f) * fmaxf(ix, 0.0f);
            float uni = vi + s_vol[j] - inter;
            s_iou[t * TK + j] = inter / fmaxf(uni, 1e-8f);
        }
    }
    __syncthreads();

    // ---------------- Phase 7: sequential NMS on warp 0 ----------------
    if (wid == 0) {
        if (lane == 0) {
            int r = 0;
            for (int i = 0; i < TK; i++) {
                int v = s_sc[i] > 0.15f;
                s_candf[i] = v && (r < NMSK);
                r += v;
            }
        }
        __syncwarp();
        for (int i = 0; i < TK; i++) {
            int keep = s_candf[i] && !s_supp[i];
            if (lane == 0) s_kept[i] = keep;
            if (keep) {
                for (int m = lane; m < TK; m += 32)
                    if (m != i && s_iou[i * TK + m] > 0.05f) s_supp[m] = 1;
            }
            __syncwarp();
        }
        if (lane == 0) {
            int nk = 0;
            for (int i = 0; i < TK; i++)
                if (s_kept[i]) s_src[nk++] = i;
            s_nk = nk;
        }
    }
    __syncthreads();

    // ---------------- Phase 8: write output (kept-first, -1 padding) ----------------
    float* ob = out + (size_t)b * TK * 8;
    if (t < TK) {
        if (t < s_nk) {
            int i = s_src[t];
            ob[t * 8 + 0] = 1.0f;
            ob[t * 8 + 1] = s_sc[i];
            ob[t * 8 + 2] = s_ctr[i][0];
            ob[t * 8 + 3] = s_ctr[i][1];
            ob[t * 8 + 4] = s_ctr[i][2];
            ob[t * 8 + 5] = s_sz[i][0];
            ob[t * 8 + 6] = s_sz[i][1];
            ob[t * 8 + 7] = s_sz[i][2];
        } else {
#pragma unroll
            for (int c = 0; c < 8; c++)
                ob[t * 8 + c] = -1.0f;
        }
    }
}

extern "C" void kernel_launch(void* const* d_in, const int* in_sizes, int n_in,
                              void* d_out, int out_size)
{
    const float* cls = (const float*)d_in[0];
    const float* shp = (const float*)d_in[1];
    const float* off = (const float*)d_in[2];
    float* out = (float*)d_out;
    detect_postproc_kernel<<<256, NT>>>(cls, shp, off, out);
}